// round 14
// baseline (speedup 1.0000x reference)
#include <cuda_runtime.h>
#include <cuda_fp16.h>
#include <cuda_fp8.h>
#include <cstdint>
#include <cstddef>

#define Bb 16
#define Tt 128
#define Dd 256
#define NTHREADS 1024

// smem layout (bytes)
#define OFF_W   0
#define SZ_W    (8 * NTHREADS * 16)        // 131072: w fp16, row j = uint4 per thread
#define OFF_A   (OFF_W + SZ_W)
#define SZ_A    (8 * NTHREADS * 8)         // 65536: alpha fp8 (x8), row j = uint2 per thread
#define OFF_YB  (OFF_A + SZ_A)
#define SZ_YB   (4 * 512)                   // own-layer y ring: 4 slots x 256 half
#define OFF_YIN (OFF_YB + SZ_YB)
#define SZ_YIN  (4 * 512)                   // L1: incoming y0 ring
#define OFF_XT  (OFF_YIN + SZ_YIN)
#define SZ_XT   (Tt * 4)
#define OFF_RED (OFF_XT + SZ_XT)
#define SZ_RED  (2 * 8 * 4)
#define OFF_MB  (OFF_RED + SZ_RED)
#define SZ_MB   (8 * 8)                     // [0..3] y0-slot (L1 side), [4..7] credits (L0 side)
#define SMEM_TOTAL (OFF_MB + SZ_MB)

__device__ __forceinline__ uint32_t my_cluster_rank() {
    uint32_t r; asm("mov.u32 %0, %%cluster_ctarank;" : "=r"(r)); return r;
}
__device__ __forceinline__ void cluster_sync_() {
    asm volatile("barrier.cluster.arrive.aligned;" ::: "memory");
    asm volatile("barrier.cluster.wait.aligned;" ::: "memory");
}
__device__ __forceinline__ uint32_t mapa_u32(uint32_t laddr, uint32_t rank) {
    uint32_t r;
    asm("mapa.shared::cluster.u32 %0, %1, %2;" : "=r"(r) : "r"(laddr), "r"(rank));
    return r;
}
__device__ __forceinline__ void st_remote_v4(uint32_t addr, uint4 v) {
    asm volatile("st.shared::cluster.v4.b32 [%0], {%1, %2, %3, %4};"
                 :: "r"(addr), "r"(v.x), "r"(v.y), "r"(v.z), "r"(v.w) : "memory");
}
__device__ __forceinline__ void mb_init(uint32_t addr, uint32_t count) {
    asm volatile("mbarrier.init.shared.b64 [%0], %1;" :: "r"(addr), "r"(count) : "memory");
}
__device__ __forceinline__ void mb_arrive_remote(uint32_t raddr) {
    asm volatile("mbarrier.arrive.release.cluster.shared::cluster.b64 _, [%0];"
                 :: "r"(raddr) : "memory");
}
__device__ __forceinline__ void mb_wait(uint32_t addr, uint32_t parity) {
    uint32_t done;
    asm volatile(
        "{\n\t.reg .pred p;\n\t"
        "mbarrier.try_wait.parity.acquire.cluster.shared::cta.b64 p, [%1], %2;\n\t"
        "selp.b32 %0, 1, 0, p;\n\t}"
        : "=r"(done) : "r"(addr), "r"(parity) : "memory");
    while (!done) {
        asm volatile(
            "{\n\t.reg .pred p;\n\t"
            "mbarrier.try_wait.parity.acquire.cluster.shared::cta.b64 p, [%1], %2, 0x989680;\n\t"
            "selp.b32 %0, 1, 0, p;\n\t}"
            : "=r"(done) : "r"(addr), "r"(parity) : "memory");
    }
}
__device__ __forceinline__ float tanh_ap(float x) {
    float y; asm("tanh.approx.f32 %0, %1;" : "=f"(y) : "f"(x)); return y;
}
__device__ __forceinline__ float grp4_sum(float v) {
    v += __shfl_xor_sync(0xffffffffu, v, 1);
    v += __shfl_xor_sync(0xffffffffu, v, 2);
    return v;
}
__device__ __forceinline__ void bar_named(int id, int n) {
    asm volatile("bar.sync %0, %1;" :: "r"(id), "r"(n) : "memory");
}
__device__ __forceinline__ __half2 cvt_e4m3x2(unsigned short s) {
    uint32_t r;
    asm("cvt.rn.f16x2.e4m3x2 %0, %1;" : "=r"(r) : "h"(s));
    return *reinterpret_cast<__half2*>(&r);
}
#define HH(u) (*reinterpret_cast<const __half2*>(&(u)))

__global__ void __launch_bounds__(NTHREADS, 1) __cluster_dims__(2, 1, 1)
plastic_kernel(const int* __restrict__ x, const float* __restrict__ emb,
               const float* __restrict__ ws, const float* __restrict__ alphas,
               const float* __restrict__ etas, float* __restrict__ out)
{
    extern __shared__ __align__(16) char smem_raw[];
    const uint32_t sbase = (uint32_t)__cvta_generic_to_shared(smem_raw);
    int*   xtok   = reinterpret_cast<int*>(smem_raw + OFF_XT);
    float* redbuf = reinterpret_cast<float*>(smem_raw + OFF_RED);

    const int tid   = threadIdx.x;
    const int batch = blockIdx.x >> 1;
    const int layer = (int)my_cluster_rank();   // rank0 = L0, rank1 = L1
    const int col   = tid >> 2;                 // 0..255
    const int dgrp  = tid & 3;                  // d-range [dgrp*64, dgrp*64+64)
    const int wid   = tid >> 5, lane = tid & 31;

#define MB_Y0(s) (sbase + OFF_MB + (uint32_t)((s) * 8))
#define MB_CR(s) (sbase + OFF_MB + 32u + (uint32_t)((s) * 8))

    // ---- init ----
    for (int i = tid; i < (SZ_YB + SZ_YIN) / 4; i += NTHREADS)
        reinterpret_cast<uint32_t*>(smem_raw + OFF_YB)[i] = 0u;
    for (int i = tid; i < Tt; i += NTHREADS) xtok[i] = x[batch * Tt + i];
    if (tid == 0)
        for (int s = 0; s < 8; s++) mb_init(sbase + OFF_MB + 8u * s, 1);
    __syncthreads();

    // ---- stage w (fp16) + alpha (fp8 e4m3, x8 scaled) ----
    // thread o = c*4 + (d>>6) owns (64 d, col c); chunk j = (d&63)>>3, byte k = d&7
    {
        const float* wsrc = ws     + (size_t)layer * Dd * Dd;
        const float* asrc = alphas + (size_t)layer * Dd * Dd;
        for (int idx = tid; idx < Dd * Dd; idx += NTHREADS) {
            int d = idx >> 8, c = idx & 255;
            int o = c * 4 + (d >> 6), j = (d & 63) >> 3, k = d & 7;
            reinterpret_cast<__half*>(smem_raw + OFF_W)[(size_t)(j * NTHREADS + o) * 8 + k] =
                __float2half(wsrc[(size_t)d * Dd + c]);
            __nv_fp8_e4m3 a8(asrc[(size_t)d * Dd + c] * 8.0f);
            smem_raw[OFF_A + (size_t)(j * NTHREADS + o) * 8 + k] =
                *reinterpret_cast<char*>(&a8);
        }
    }
    __syncthreads();

    const float eta = etas[layer];
    const __half2 om2 = __float2half2_rn(1.0f - eta);
    __half2 h2[32];   // hebb/8 (fp16), 64 entries
#pragma unroll
    for (int i = 0; i < 32; i++) h2[i] = __float2half2_rn(0.f);

    const uint32_t del_peer = mapa_u32(sbase, (uint32_t)(layer ^ 1)) - sbase;
    cluster_sync_();   // barriers armed everywhere before any arrive

    float* const outB = out + (size_t)batch * Tt * Dd;
    float embreg = (layer == 0) ? __ldg(&emb[(size_t)xtok[0] * Dd + col]) : 0.f;

    const uint4* wp = reinterpret_cast<const uint4*>(smem_raw + OFF_W) + tid;
    const uint2* ap = reinterpret_cast<const uint2*>(smem_raw + OFF_A) + tid;

    for (int t = 0; t < Tt; ++t) {
        const int sc = t & 3, sp = (t + 3) & 3;

        // ---- the ONLY cross-CTA waits: one-directional pipeline ----
        if (layer == 1)      mb_wait(MB_Y0(sc), (uint32_t)((t >> 2) & 1));
        else if (t >= 4)     mb_wait(MB_CR(sc), (uint32_t)(((t - 4) >> 2) & 1));

        // ---- dot over own 64 d's for own col (y from local slot sp) ----
        const uint4* yp = reinterpret_cast<const uint4*>(smem_raw + OFF_YB + sp * 512)
                          + dgrp * 8;
        __half2 acc0 = __float2half2_rn(0.f), acc1 = acc0, acc2 = acc0, acc3 = acc0;
#pragma unroll
        for (int j = 0; j < 8; j++) {
            uint4 wv = wp[j * NTHREADS];
            uint2 av = ap[j * NTHREADS];
            uint4 yv = yp[j];
            __half2 a01 = cvt_e4m3x2((unsigned short)av.x);
            __half2 a23 = cvt_e4m3x2((unsigned short)(av.x >> 16));
            __half2 a45 = cvt_e4m3x2((unsigned short)av.y);
            __half2 a67 = cvt_e4m3x2((unsigned short)(av.y >> 16));
            acc0 = __hfma2(HH(yv.x), __hfma2(a01, h2[4 * j + 0], HH(wv.x)), acc0);
            acc1 = __hfma2(HH(yv.y), __hfma2(a23, h2[4 * j + 1], HH(wv.y)), acc1);
            acc2 = __hfma2(HH(yv.z), __hfma2(a45, h2[4 * j + 2], HH(wv.z)), acc2);
            acc3 = __hfma2(HH(yv.w), __hfma2(a67, h2[4 * j + 3], HH(wv.w)), acc3);
        }
        float2 f = __half22float2(__hadd2(__hadd2(acc0, acc1), __hadd2(acc2, acc3)));
        float acc = grp4_sum(f.x + f.y);
        float inp = (layer == 0)
            ? embreg
            : __half2float(reinterpret_cast<const __half*>(smem_raw + OFF_YIN + sc * 512)[col]);
        float y = tanh_ap(acc + inp);
        if (dgrp == 0)
            reinterpret_cast<__half*>(smem_raw + OFF_YB + sc * 512)[col] = __float2half(y);

        // ---- hebb (h/8): h' = om*h + (eta*y/8)*yin ; pre-sync, reads slot sp ----
        {
            __half2 ey2 = __float2half2_rn(eta * y * 0.125f);
#pragma unroll
            for (int j = 0; j < 8; j++) {
                uint4 yv = yp[j];
                h2[4 * j + 0] = __hfma2(h2[4 * j + 0], om2, __hmul2(HH(yv.x), ey2));
                h2[4 * j + 1] = __hfma2(h2[4 * j + 1], om2, __hmul2(HH(yv.y), ey2));
                h2[4 * j + 2] = __hfma2(h2[4 * j + 2], om2, __hmul2(HH(yv.z), ey2));
                h2[4 * j + 3] = __hfma2(h2[4 * j + 3], om2, __hmul2(HH(yv.w), ey2));
            }
        }
        if (layer == 0 && t + 1 < Tt)
            embreg = __ldg(&emb[(size_t)xtok[t + 1] * Dd + col]);

        __syncthreads();   // y(t) slab complete & visible CTA-wide

        if (layer == 0) {
            // ship y0(t) to L1's slot sc: warp 0, 32 x 16B + one release-arrive
            if (wid == 0) {
                uint4 v = *reinterpret_cast<const uint4*>(smem_raw + OFF_YB
                                                          + sc * 512 + lane * 16);
                st_remote_v4(sbase + OFF_YIN + (uint32_t)(sc * 512 + lane * 16)
                             + del_peer, v);
                __syncwarp();
                if (lane == 0) mb_arrive_remote(MB_Y0(sc) + del_peer);
            }
        } else {
            if (tid == 0) mb_arrive_remote(MB_CR(sc) + del_peer);  // slot sc consumed
            // softmax(sigmoid(y1(t))) -> out[t], warps 0..7 only
            if (tid < Dd) {
                float* rb = redbuf + (t & 1) * 8;
                float v = __half2float(
                    reinterpret_cast<const __half*>(smem_raw + OFF_YB + sc * 512)[tid]);
                float ex = __expf(__fdividef(1.0f, 1.0f + __expf(-v)));
                float w0 = ex;
#pragma unroll
                for (int o = 16; o >= 1; o >>= 1)
                    w0 += __shfl_xor_sync(0xffffffffu, w0, o);
                if (lane == 0) rb[wid] = w0;
                bar_named(1, 256);
                float tot = 0.f;
#pragma unroll
                for (int k = 0; k < 8; k++) tot += rb[k];
                outB[(size_t)t * Dd + tid] = __fdividef(ex, tot);
            }
        }
    }

    cluster_sync_();   // L0 must outlive L1's last credit arrive
}

extern "C" void kernel_launch(void* const* d_in, const int* in_sizes, int n_in,
                              void* d_out, int out_size) {
    const int*   x      = (const int*)d_in[0];
    const float* emb    = (const float*)d_in[1];
    const float* ws     = (const float*)d_in[2];
    const float* alphas = (const float*)d_in[3];
    const float* etas   = (const float*)d_in[4];
    cudaFuncSetAttribute(plastic_kernel,
                         cudaFuncAttributeMaxDynamicSharedMemorySize, SMEM_TOTAL);
    plastic_kernel<<<Bb * 2, NTHREADS, SMEM_TOTAL>>>(
        x, emb, ws, alphas, etas, (float*)d_out);
}

// round 15
// speedup vs baseline: 2.5170x; 2.5170x over previous
#include <cuda_runtime.h>
#include <cuda_fp16.h>
#include <cstdint>
#include <cstddef>

#define Bb 16
#define Tt 128
#define Dd 256
#define HCOLS 128
#define NTHREADS 1024

// smem layout (bytes)
#define OFF_WA   0
#define SZ_WA    (8 * NTHREADS * 16)       // 131072: fp16 w+alpha interleaved uint4 rows
#define OFF_YB   (OFF_WA + SZ_WA)
#define YSLOT_H  320                        // halves per slot: 8 chunks of (32 data + 8 pad)
#define SZ_YB    (2 * 4 * YSLOT_H * 2)      // 5120
#define OFF_Y0H  (OFF_YB + SZ_YB)
#define SZ_Y0H   (2 * 4 * HCOLS * 2)        // 2048
#define OFF_XT   (OFF_Y0H + SZ_Y0H)
#define SZ_XT    (2 * Tt * 4)               // 1024
#define OFF_RED  (OFF_XT + SZ_XT)
#define SZ_RED   (32 * 4)                   // redbuf[2 parities][16]
#define OFF_MB   (OFF_RED + SZ_RED)
#define SZ_MB    (4 * 8)                    // 4 slot barriers
#define SMEM_TOTAL (OFF_MB + SZ_MB)

__device__ __forceinline__ uint32_t my_cluster_rank() {
    uint32_t r; asm("mov.u32 %0, %%cluster_ctarank;" : "=r"(r)); return r;
}
__device__ __forceinline__ void cluster_sync_() {
    asm volatile("barrier.cluster.arrive.aligned;" ::: "memory");
    asm volatile("barrier.cluster.wait.aligned;" ::: "memory");
}
__device__ __forceinline__ uint32_t mapa_u32(uint32_t laddr, uint32_t rank) {
    uint32_t r;
    asm("mapa.shared::cluster.u32 %0, %1, %2;" : "=r"(r) : "r"(laddr), "r"(rank));
    return r;
}
__device__ __forceinline__ void st_remote_v4(uint32_t addr, uint4 v) {
    asm volatile("st.shared::cluster.v4.b32 [%0], {%1, %2, %3, %4};"
                 :: "r"(addr), "r"(v.x), "r"(v.y), "r"(v.z), "r"(v.w) : "memory");
}
__device__ __forceinline__ void mb_init(uint32_t addr, uint32_t count) {
    asm volatile("mbarrier.init.shared.b64 [%0], %1;" :: "r"(addr), "r"(count) : "memory");
}
__device__ __forceinline__ void mb_arrive_remote(uint32_t raddr) {
    asm volatile("mbarrier.arrive.release.cluster.shared::cluster.b64 _, [%0];"
                 :: "r"(raddr) : "memory");
}
__device__ __forceinline__ void mb_wait(uint32_t addr, uint32_t parity) {
    uint32_t done;
    asm volatile(
        "{\n\t.reg .pred p;\n\t"
        "mbarrier.try_wait.parity.acquire.cluster.shared::cta.b64 p, [%1], %2;\n\t"
        "selp.b32 %0, 1, 0, p;\n\t}"
        : "=r"(done) : "r"(addr), "r"(parity) : "memory");
    while (!done) {
        asm volatile(
            "{\n\t.reg .pred p;\n\t"
            "mbarrier.try_wait.parity.acquire.cluster.shared::cta.b64 p, [%1], %2, 0x989680;\n\t"
            "selp.b32 %0, 1, 0, p;\n\t}"
            : "=r"(done) : "r"(addr), "r"(parity) : "memory");
    }
}
__device__ __forceinline__ float tanh_ap(float x) {
    float y; asm("tanh.approx.f32 %0, %1;" : "=f"(y) : "f"(x)); return y;
}
__device__ __forceinline__ float grp8_sum(float v) {
    v += __shfl_xor_sync(0xffffffffu, v, 1);
    v += __shfl_xor_sync(0xffffffffu, v, 2);
    v += __shfl_xor_sync(0xffffffffu, v, 4);
    return v;
}
__device__ __forceinline__ void bar_named(int id, int n) {
    asm volatile("bar.sync %0, %1;" :: "r"(id), "r"(n) : "memory");
}

__global__ void __launch_bounds__(NTHREADS, 1) __cluster_dims__(4, 1, 1)
plastic_kernel(const int* __restrict__ x, const float* __restrict__ emb,
               const float* __restrict__ ws, const float* __restrict__ alphas,
               const float* __restrict__ etas, float* __restrict__ out)
{
    extern __shared__ __align__(16) char smem_raw[];
    uint4*  wa     = reinterpret_cast<uint4*>(smem_raw + OFF_WA);    // [8][1024]
    __half* ybuf   = reinterpret_cast<__half*>(smem_raw + OFF_YB);   // [2][4][320]
    __half* y0h    = reinterpret_cast<__half*>(smem_raw + OFF_Y0H);  // [2][4][128]
    int*    xtok   = reinterpret_cast<int*>(smem_raw + OFF_XT);      // [2][128]
    float*  redbuf = reinterpret_cast<float*>(smem_raw + OFF_RED);   // [2][16]
    const uint32_t sbase = (uint32_t)__cvta_generic_to_shared(smem_raw);

    const int tid     = threadIdx.x;
    const int cluster = blockIdx.x >> 2;
    const int rank    = (int)my_cluster_rank();
    const int layer   = rank >> 1;
    const int half_   = rank & 1;
    const int col_off = half_ * HCOLS;
    const int partner = rank ^ 1;
    const int col     = tid >> 3;            // 0..127
    const int colg    = col_off + col;
    const int dgrp    = tid & 7;             // 0..7, d-range [dgrp*32, dgrp*32+32)
    const int wid     = tid >> 5, lane = tid & 31;
    const int pcol    = (colg >> 5) * 40 + (colg & 31);   // write pos for y[colg]
    const int ptid    = (tid >> 5) * 40 + (tid & 31);     // softmax read pos (tid<256)

#define MB_ADDR(s)     (sbase + OFF_MB + (uint32_t)((s) * 8))
#define YB_SLOT(b, s)  (ybuf + ((b) * 4 + (s)) * YSLOT_H)
#define Y0H_SLOT(b, s) (y0h + ((b) * 4 + (s)) * HCOLS)

    // ---- init shared ----
    for (int i = tid; i < 2 * 4 * YSLOT_H; i += NTHREADS) ybuf[i] = __ushort_as_half(0);
    for (int i = tid; i < 2 * 4 * HCOLS; i += NTHREADS) y0h[i] = __ushort_as_half(0);
    for (int i = tid; i < 2 * Tt; i += NTHREADS)
        xtok[i] = x[(cluster * 2 + (i >> 7)) * Tt + (i & 127)];
    if (tid == 0)
        for (int k = 0; k < 4; k++) mb_init(MB_ADDR(k), 2);
    __syncthreads();

    const float eta = etas[layer];
    const __half2 om2 = __float2half2_rn(1.0f - eta);

    __half2 h2a[16], h2b[16];
#pragma unroll
    for (int i = 0; i < 16; i++) { h2a[i] = __float2half2_rn(0.f); h2b[i] = h2a[i]; }

    // ---- stage w + alpha (fp16): thread o = c*8 + (d>>5) owns (32 d, 1 col) ----
    {
        const float* wsrc = ws     + (size_t)layer * Dd * Dd;
        const float* asrc = alphas + (size_t)layer * Dd * Dd;
        for (int idx = tid; idx < Dd * HCOLS; idx += NTHREADS) {
            int d = idx >> 7, c = idx & 127;
            int o = c * 8 + (d >> 5);
            int j = (d & 31) >> 3;
            int k = d & 7;
            reinterpret_cast<__half*>(&wa[(2 * j) * NTHREADS + o])[k] =
                __float2half(wsrc[(size_t)d * Dd + col_off + c]);
            reinterpret_cast<__half*>(&wa[(2 * j + 1) * NTHREADS + o])[k] =
                __float2half(asrc[(size_t)d * Dd + col_off + c]);
        }
    }
    __syncthreads();

    const uint32_t del_partner = mapa_u32(sbase, (uint32_t)partner) - sbase;
    const uint32_t del_inter   = (layer == 0)
        ? (mapa_u32(sbase, (uint32_t)(rank + 2)) - sbase)
        : (mapa_u32(sbase, (uint32_t)(rank - 2)) - sbase);

    cluster_sync_();   // barriers armed + buffers zeroed everywhere

    // ---- startup arrives (count=2 per slot-phase) ----
    if (tid == 0)
        mb_arrive_remote(MB_ADDR(0) + del_partner);
    if (tid == 32 && layer == 1) {   // credits to my L0 for slots 0..3
#pragma unroll
        for (int s = 0; s < 4; s++)
            mb_arrive_remote(MB_ADDR(s) + del_inter);
    }

    float* const outB0 = out + (size_t)(cluster * 2 + 0) * Tt * Dd;
    float* const outB1 = out + (size_t)(cluster * 2 + 1) * Tt * Dd;
    const uint4* wthr = wa + tid;

    float embreg0 = 0.f, embreg1 = 0.f;
    if (layer == 0) {
        embreg0 = __ldg(&emb[(size_t)xtok[0] * Dd + colg]);
        embreg1 = __ldg(&emb[(size_t)xtok[Tt] * Dd + colg]);
    }

    for (int t = 0; t < Tt; ++t) {
        const int sc = t & 3, sp = (t + 3) & 3, n3 = (t + 1) & 3;
        const uint32_t par = (uint32_t)((t >> 2) & 1);

        mb_wait(MB_ADDR(sc), par);   // one wait: partner(t-1) + inter(y0 data / credit)

        // ---- fused dual-batch dot: w/alpha loaded once ----
        const uint4* yp0 = reinterpret_cast<const uint4*>(YB_SLOT(0, sp)) + dgrp * 5;
        const uint4* yp1 = reinterpret_cast<const uint4*>(YB_SLOT(1, sp)) + dgrp * 5;
        __half2 accA0 = __float2half2_rn(0.f), accA1 = accA0;
        __half2 accB0 = accA0, accB1 = accA0;
#pragma unroll
        for (int j = 0; j < 4; j++) {
            uint4 wv = wthr[(2 * j) * NTHREADS];
            uint4 av = wthr[(2 * j + 1) * NTHREADS];
            uint4 y0v = yp0[j];
            uint4 y1v = yp1[j];
#define LANE(F)  F(x, 4 * j + 0, accA0, accB0)  F(y, 4 * j + 1, accA1, accB1) \
                 F(z, 4 * j + 2, accA0, accB0)  F(w, 4 * j + 3, accA1, accB1)
#define DOT2(c, hi, aA, aB)                                                        \
            {                                                                      \
                __half2 wl = *reinterpret_cast<__half2*>(&wv.c);                   \
                __half2 al = *reinterpret_cast<__half2*>(&av.c);                   \
                aA = __hfma2(*reinterpret_cast<__half2*>(&y0v.c),                  \
                             __hfma2(al, h2a[hi], wl), aA);                        \
                aB = __hfma2(*reinterpret_cast<__half2*>(&y1v.c),                  \
                             __hfma2(al, h2b[hi], wl), aB);                        \
            }
            LANE(DOT2)
#undef DOT2
#undef LANE
        }
        float2 fA = __half22float2(__hadd2(accA0, accA1));
        float2 fB = __half22float2(__hadd2(accB0, accB1));
        float acc0 = grp8_sum(fA.x + fA.y);
        float acc1 = grp8_sum(fB.x + fB.y);

        float inp0 = (layer == 0) ? embreg0 : __half2float(Y0H_SLOT(0, sc)[col]);
        float inp1 = (layer == 0) ? embreg1 : __half2float(Y0H_SLOT(1, sc)[col]);
        float y0 = tanh_ap(acc0 + inp0);
        float y1 = tanh_ap(acc1 + inp1);

        // ---- local y writes only (one thread per column) ----
        if (dgrp == 0) {
            YB_SLOT(0, sc)[pcol] = __float2half(y0);
            YB_SLOT(1, sc)[pcol] = __float2half(y1);
        }
        __syncthreads();   // local slab complete & visible

        // ---- vectorized exchange: warp 0 -> partner, warp 1 -> inter ----
        if (wid == 0) {
            const int B = lane >> 4, l = lane & 15;
            const int ch = half_ * 4 + (l >> 2), q = l & 3;
            const char* src = reinterpret_cast<const char*>(YB_SLOT(B, sc))
                              + ch * 80 + q * 16;
            uint4 v = *reinterpret_cast<const uint4*>(src);
            st_remote_v4((uint32_t)__cvta_generic_to_shared(src) + del_partner, v);
            __syncwarp();
            if (lane == 0) mb_arrive_remote(MB_ADDR(n3) + del_partner);
        } else if (wid == 1) {
            if (layer == 0) {
                const int B = lane >> 4, l = lane & 15;
                const int ch = half_ * 4 + (l >> 2), q = l & 3;
                const char* src = reinterpret_cast<const char*>(YB_SLOT(B, sc))
                                  + ch * 80 + q * 16;
                uint4 v = *reinterpret_cast<const uint4*>(src);
                char* dst = reinterpret_cast<char*>(Y0H_SLOT(B, sc)) + l * 16;
                st_remote_v4((uint32_t)__cvta_generic_to_shared(dst) + del_inter, v);
                __syncwarp();
            }
            if (lane == 0) mb_arrive_remote(MB_ADDR(sc) + del_inter);
        }

        // ---- deferred: hebb (re-reads old y), emb prefetch, softmax ----
        {
            __half2 ey0 = __float2half2_rn(eta * y0);
            __half2 ey1 = __float2half2_rn(eta * y1);
#pragma unroll
            for (int j = 0; j < 4; j++) {
                uint4 y0v = yp0[j];
                uint4 y1v = yp1[j];
#define HEB(c, hi)                                                                 \
                h2a[hi] = __hfma2(h2a[hi], om2,                                    \
                    __hmul2(*reinterpret_cast<__half2*>(&y0v.c), ey0));            \
                h2b[hi] = __hfma2(h2b[hi], om2,                                    \
                    __hmul2(*reinterpret_cast<__half2*>(&y1v.c), ey1));
                HEB(x, 4 * j + 0) HEB(y, 4 * j + 1) HEB(z, 4 * j + 2) HEB(w, 4 * j + 3)
#undef HEB
            }
        }
        if (layer == 0 && t + 1 < Tt) {
            embreg0 = __ldg(&emb[(size_t)xtok[t + 1] * Dd + colg]);
            embreg1 = __ldg(&emb[(size_t)xtok[Tt + t + 1] * Dd + colg]);
        }

        // ---- softmax: warps 0..7 only, named barrier (others run ahead) ----
        if (layer == 1 && t >= 1 && tid < 256) {
            float* rb = redbuf + (t & 1) * 16;
            float v0 = __half2float(YB_SLOT(0, sp)[ptid]);
            float v1 = __half2float(YB_SLOT(1, sp)[ptid]);
            float ex0 = __expf(__fdividef(1.0f, 1.0f + __expf(-v0)));
            float ex1 = __expf(__fdividef(1.0f, 1.0f + __expf(-v1)));
            float w0 = ex0, w1 = ex1;
#pragma unroll
            for (int o = 16; o >= 1; o >>= 1) {
                w0 += __shfl_xor_sync(0xffffffffu, w0, o);
                w1 += __shfl_xor_sync(0xffffffffu, w1, o);
            }
            if (lane == 0) { rb[wid] = w0; rb[8 + wid] = w1; }
            bar_named(1, 256);
            float t0 = 0.f, t1 = 0.f;
#pragma unroll
            for (int k = 0; k < 8; k++) { t0 += rb[k]; t1 += rb[8 + k]; }
            if (tid >= col_off && tid < col_off + HCOLS) {
                outB0[(size_t)(t - 1) * Dd + tid] = __fdividef(ex0, t0);
                outB1[(size_t)(t - 1) * Dd + tid] = __fdividef(ex1, t1);
            }
        }
    }

    // ---- epilogue ----
    if (layer == 0) {
        if (tid == 32)   // bonus inter so L1's final slot-0 phase completes
            mb_arrive_remote(MB_ADDR(0) + del_inter);
    } else {
        mb_wait(MB_ADDR(0), 0u);
        if (tid < 256) {
            const int sp = 3;   // slot of y1(127)
            float* rb = redbuf;  // parity-0 half; last loop softmax used parity 1
            float v0 = __half2float(YB_SLOT(0, sp)[ptid]);
            float v1 = __half2float(YB_SLOT(1, sp)[ptid]);
            float ex0 = __expf(__fdividef(1.0f, 1.0f + __expf(-v0)));
            float ex1 = __expf(__fdividef(1.0f, 1.0f + __expf(-v1)));
            float w0 = ex0, w1 = ex1;
#pragma unroll
            for (int o = 16; o >= 1; o >>= 1) {
                w0 += __shfl_xor_sync(0xffffffffu, w0, o);
                w1 += __shfl_xor_sync(0xffffffffu, w1, o);
            }
            if (lane == 0) { rb[wid] = w0; rb[8 + wid] = w1; }
            bar_named(1, 256);
            float t0 = 0.f, t1 = 0.f;
#pragma unroll
            for (int k = 0; k < 8; k++) { t0 += rb[k]; t1 += rb[8 + k]; }
            if (tid >= col_off && tid < col_off + HCOLS) {
                outB0[(size_t)(Tt - 1) * Dd + tid] = __fdividef(ex0, t0);
                outB1[(size_t)(Tt - 1) * Dd + tid] = __fdividef(ex1, t1);
            }
        }
    }

    cluster_sync_();
}

extern "C" void kernel_launch(void* const* d_in, const int* in_sizes, int n_in,
                              void* d_out, int out_size) {
    const int*   x      = (const int*)d_in[0];
    const float* emb    = (const float*)d_in[1];
    const float* ws     = (const float*)d_in[2];
    const float* alphas = (const float*)d_in[3];
    const float* etas   = (const float*)d_in[4];
    cudaFuncSetAttribute(plastic_kernel,
                         cudaFuncAttributeMaxDynamicSharedMemorySize, SMEM_TOTAL);
    plastic_kernel<<<(Bb / 2) * 4, NTHREADS, SMEM_TOTAL>>>(
        x, emb, ws, alphas, etas, (float*)d_out);
}